// round 15
// baseline (speedup 1.0000x reference)
#include <cuda_runtime.h>
#include <cuda_fp16.h>
#include <math.h>
#include <stdint.h>

// Problem constants
#define Bn 8
#define Nn 2048
#define Cn 1024
#define Mrows (Bn*Nn)   // 16384
#define NPART 32        // stats partials: 16 j-tiles x 2 warp-columns
#define MCHUNK 64       // mean partial chunks (32 rows each)

// ---------------- scratch (device globals) ----------------
__device__ __half g_xh[(size_t)Mrows * Cn];            // 32 MB: fp16(x)
__device__ __half g_wth[(size_t)2048 * 1024];          // 4 MB: fp16([Wq,Wk]^T) [j][k]
__device__ __half g_wvh[(size_t)1024 * 1024];          // 2 MB: fp16(Wv) [cin][cout]
__device__ __half g_pwh[(size_t)1024 * 1024];          // 2 MB: fp16(proj_w^T) [j][k]
__device__ __half g_pw2h[(size_t)Bn * 1024 * 1024];    // 16 MB: fp16(proj^T * chw[b])
__device__ __half g_mbh[(size_t)Bn * 1024 * 1024];     // 16 MB: fp16(M_b^T[j][cin])
__device__ float g_y[(size_t)Mrows * Cn];              // 64 MB: y = x @ M_b (pre-softmax-scale)
__device__ float g_stats[(size_t)NPART * Mrows * 5];
__device__ float g_mpart[MCHUNK * Bn * Cn];
__device__ float g_m[Bn * Cn];
__device__ float g_h[Bn * 256];
__device__ float g_A[Mrows];
__device__ float g_w[Mrows];
__device__ float g_chw[Bn * Cn];

// ---------------- helpers ----------------
__device__ __forceinline__ uint32_t smem_u32(const void* p) {
    uint32_t a;
    asm("{ .reg .u64 t; cvta.to.shared.u64 t, %1; cvt.u32.u64 %0, t; }" : "=r"(a) : "l"(p));
    return a;
}
__device__ __forceinline__ void cp16(uint32_t dst, const void* src) {
    asm volatile("cp.async.cg.shared.global [%0], [%1], 16;" :: "r"(dst), "l"(src));
}
__device__ __forceinline__ void cp_commit() { asm volatile("cp.async.commit_group;" ::: "memory"); }
template<int N> __device__ __forceinline__ void cp_wait() {
    asm volatile("cp.async.wait_group %0;" :: "n"(N) : "memory");
}
__device__ __forceinline__ void ldsm4(uint32_t* r, uint32_t a) {
    asm volatile("ldmatrix.sync.aligned.m8n8.x4.shared.b16 {%0,%1,%2,%3}, [%4];"
                 : "=r"(r[0]), "=r"(r[1]), "=r"(r[2]), "=r"(r[3]) : "r"(a));
}
__device__ __forceinline__ void mma16(float* d, const uint32_t* a, const uint32_t* b) {
    asm volatile(
        "mma.sync.aligned.m16n8k16.row.col.f32.f16.f16.f32 "
        "{%0,%1,%2,%3}, {%4,%5,%6,%7}, {%8,%9}, {%0,%1,%2,%3};"
        : "+f"(d[0]), "+f"(d[1]), "+f"(d[2]), "+f"(d[3])
        : "r"(a[0]), "r"(a[1]), "r"(a[2]), "r"(a[3]), "r"(b[0]), "r"(b[1]));
}
__device__ __forceinline__ float warp_sum(float v) {
    #pragma unroll
    for (int off = 16; off > 0; off >>= 1)
        v += __shfl_xor_sync(0xffffffffu, v, off);
    return v;
}

// =====================================================================
// fused: column-sum partials of x over n (32-row chunks) + fp16 conversion
// =====================================================================
__global__ void k_mean_prep(const float* __restrict__ x)
{
    int p = blockIdx.x, b = blockIdx.y, c = threadIdx.x;
    const size_t base = ((size_t)b * Nn + p * 32) * Cn + c;
    float s = 0.f;
    #pragma unroll 4
    for (int n = 0; n < 32; n++) {
        float v = x[base + (size_t)n * Cn];
        s += v;
        g_xh[base + (size_t)n * Cn] = __float2half_rn(v);
    }
    g_mpart[(p * Bn + b) * Cn + c] = s;
}

// =====================================================================
// weight preps
// =====================================================================
__global__ void k_prep_w(const float* __restrict__ w) {   // qkv_w cols 0..2047 -> g_wth[2048][1024]
    __shared__ float t[32][33];
    int j0 = blockIdx.x * 32, k0 = blockIdx.y * 32;
    int tx = threadIdx.x, ty = threadIdx.y;
    #pragma unroll
    for (int l = 0; l < 4; l++)
        t[ty + l * 8][tx] = w[(size_t)(k0 + ty + l * 8) * 3072 + j0 + tx];
    __syncthreads();
    #pragma unroll
    for (int l = 0; l < 4; l++)
        g_wth[(size_t)(j0 + ty + l * 8) * 1024 + k0 + tx] = __float2half_rn(t[tx][ty + l * 8]);
}
__global__ void k_prep_wv(const float* __restrict__ w) {  // qkv_w cols 2048.. -> g_wvh[cin][cout]
    int cin = blockIdx.x;
    int c4 = threadIdx.x * 4;
    float4 v = *(const float4*)(w + (size_t)cin * 3072 + 2048 + c4);
    *(__half2*)(g_wvh + (size_t)cin * 1024 + c4)     = __floats2half2_rn(v.x, v.y);
    *(__half2*)(g_wvh + (size_t)cin * 1024 + c4 + 2) = __floats2half2_rn(v.z, v.w);
}
__global__ void k_prep_pwT(const float* __restrict__ pw) { // [1024][1024] -> g_pwh[j][k]
    __shared__ float t[32][33];
    int j0 = blockIdx.x * 32, k0 = blockIdx.y * 32;
    int tx = threadIdx.x, ty = threadIdx.y;
    #pragma unroll
    for (int l = 0; l < 4; l++)
        t[ty + l * 8][tx] = pw[(size_t)(k0 + ty + l * 8) * 1024 + j0 + tx];
    __syncthreads();
    #pragma unroll
    for (int l = 0; l < 4; l++)
        g_pwh[(size_t)(j0 + ty + l * 8) * 1024 + k0 + tx] = __float2half_rn(t[tx][ty + l * 8]);
}
// g_pw2h[b][j][k] = g_pwh[j][k] * chw[b][k]
__global__ void k_scale_pw()
{
    int j = blockIdx.x, b = blockIdx.y;
    int k4 = threadIdx.x * 4;
    __half2 p0 = *(__half2*)(g_pwh + (size_t)j * 1024 + k4);
    __half2 p1 = *(__half2*)(g_pwh + (size_t)j * 1024 + k4 + 2);
    float4 cw = *(const float4*)(g_chw + b * Cn + k4);
    float2 f0 = __half22float2(p0);
    float2 f1 = __half22float2(p1);
    __half* dst = g_pw2h + ((size_t)b * 1024 + j) * 1024 + k4;
    *(__half2*)dst       = __floats2half2_rn(f0.x * cw.x, f0.y * cw.y);
    *(__half2*)(dst + 2) = __floats2half2_rn(f1.x * cw.z, f1.y * cw.w);
}

// =====================================================================
// channel gate
// =====================================================================
__global__ void k_chm()
{
    int b = blockIdx.x, c = threadIdx.x;
    float s = 0.f;
    #pragma unroll
    for (int p = 0; p < MCHUNK; p++) s += g_mpart[(p * Bn + b) * Cn + c];
    g_m[b * Cn + c] = s * (1.0f / (float)Nn);
}

__global__ __launch_bounds__(256)
void k_ch1(const float* __restrict__ w1, const float* __restrict__ b1)
{
    const int b = blockIdx.y;
    const int j = blockIdx.x * 8 + (threadIdx.x >> 5);
    const int lane = threadIdx.x & 31;
    float s = 0.f;
    #pragma unroll 8
    for (int i = 0; i < 32; i++) {
        int c = lane + i * 32;
        s = fmaf(g_m[b * Cn + c], w1[c * 256 + j], s);
    }
    s = warp_sum(s);
    if (lane == 0) g_h[b * 256 + j] = fmaxf(s + b1[j], 0.f);
}

__global__ __launch_bounds__(256)
void k_ch2(const float* __restrict__ w2, const float* __restrict__ b2)
{
    const int b = blockIdx.y;
    const int c = blockIdx.x * 8 + (threadIdx.x >> 5);
    const int lane = threadIdx.x & 31;
    float s = 0.f;
    #pragma unroll
    for (int i = 0; i < 8; i++) {
        int j = lane + i * 32;
        s = fmaf(g_h[b * 256 + j], w2[j * 1024 + c], s);
    }
    s = warp_sum(s);
    if (lane == 0) g_chw[b * Cn + c] = 1.0f / (1.0f + expf(-(s + b2[c])));
}

// =====================================================================
// GEMM-QK (fp16 mma.sync): q,k = x @ [Wq,Wk]; stats only
// =====================================================================
#define QK_A 18432
#define QK_B 9216
#define QK_STAGE (QK_A + 2*QK_B)   // 36864
#define QK_NS 3
#define KITER 16

__device__ __forceinline__ void qk_fill(uint32_t sbase, int k0, int row0, int j0, int tid)
{
    #pragma unroll
    for (int i = 0; i < 4; i++) {
        int e = tid + i * 256;
        int r = e >> 3, c = e & 7;
        cp16(sbase + r * 144 + c * 16, g_xh + (size_t)(row0 + r) * 1024 + k0 + c * 8);
    }
    #pragma unroll
    for (int i = 0; i < 4; i++) {
        int e = tid + i * 256;
        int t = e >> 9, rr = (e >> 3) & 63, c = e & 7;
        cp16(sbase + QK_A + t * QK_B + rr * 144 + c * 16,
             g_wth + (size_t)(t * 1024 + j0 + rr) * 1024 + k0 + c * 8);
    }
    cp_commit();
}

__global__ __launch_bounds__(256, 2)
void k_gemm_qk()
{
    extern __shared__ __align__(128) char smem[];
    const uint32_t sb = smem_u32(smem);
    const int tid = threadIdx.x;
    const int wid = tid >> 5, lane = tid & 31;
    const int wm = wid & 3, wn = wid >> 2;
    const int grp = lane >> 2, qd = lane & 3;
    const int lr = lane & 15, lc = lane >> 4;
    const int j0 = blockIdx.x * 64;
    const int row0 = blockIdx.y * 128;

    float acc[2][2][4][4];
    #pragma unroll
    for (int t = 0; t < 2; t++)
        #pragma unroll
        for (int mi = 0; mi < 2; mi++)
            #pragma unroll
            for (int ni = 0; ni < 4; ni++)
                #pragma unroll
                for (int j = 0; j < 4; j++) acc[t][mi][ni][j] = 0.f;

    qk_fill(sb + 0 * QK_STAGE, 0,  row0, j0, tid);
    qk_fill(sb + 1 * QK_STAGE, 64, row0, j0, tid);

    for (int it = 0; it < KITER; ++it) {
        cp_wait<QK_NS - 2>();
        __syncthreads();
        int fc = it + QK_NS - 1;
        if (fc < KITER) qk_fill(sb + (fc % QK_NS) * QK_STAGE, fc * 64, row0, j0, tid);
        else cp_commit();

        const uint32_t Ab = sb + (it % QK_NS) * QK_STAGE;
        const uint32_t Bb = Ab + QK_A;
        #pragma unroll
        for (int kk = 0; kk < 4; kk++) {
            uint32_t a[2][4];
            #pragma unroll
            for (int mi = 0; mi < 2; mi++)
                ldsm4(a[mi], Ab + (uint32_t)((wm * 32 + mi * 16 + lr) * 144 + (kk * 2 + lc) * 16));
            #pragma unroll
            for (int t = 0; t < 2; t++) {
                #pragma unroll
                for (int hh = 0; hh < 2; hh++) {
                    uint32_t bb[4];
                    ldsm4(bb, Bb + (uint32_t)(t * QK_B + (wn * 32 + hh * 16 + lr) * 144 + (kk * 2 + lc) * 16));
                    uint32_t b0[2] = {bb[0], bb[2]};
                    uint32_t b1[2] = {bb[1], bb[3]};
                    #pragma unroll
                    for (int mi = 0; mi < 2; mi++) {
                        mma16(acc[t][mi][hh * 2],     a[mi], b0);
                        mma16(acc[t][mi][hh * 2 + 1], a[mi], b1);
                    }
                }
            }
        }
    }

    const int p = blockIdx.x * 2 + wn;
    #pragma unroll
    for (int mi = 0; mi < 2; mi++) {
        #pragma unroll
        for (int h = 0; h < 2; h++) {
            float sq = 0.f, sk = 0.f, sqq = 0.f, skk = 0.f, sqk = 0.f;
            #pragma unroll
            for (int ni = 0; ni < 4; ni++) {
                #pragma unroll
                for (int j = 0; j < 2; j++) {
                    float q = acc[0][mi][ni][h * 2 + j];
                    float k = acc[1][mi][ni][h * 2 + j];
                    sq += q; sk += k; sqq += q * q; skk += k * k; sqk += q * k;
                }
            }
            #pragma unroll
            for (int off = 1; off <= 2; off <<= 1) {
                sq  += __shfl_xor_sync(0xffffffffu, sq,  off);
                sk  += __shfl_xor_sync(0xffffffffu, sk,  off);
                sqq += __shfl_xor_sync(0xffffffffu, sqq, off);
                skk += __shfl_xor_sync(0xffffffffu, skk, off);
                sqk += __shfl_xor_sync(0xffffffffu, sqk, off);
            }
            if (qd == 0) {
                int row = row0 + wm * 32 + mi * 16 + grp + h * 8;
                float* d = g_stats + ((size_t)p * Mrows + row) * 5;
                d[0] = sq; d[1] = sk; d[2] = sqq; d[3] = skk; d[4] = sqk;
            }
        }
    }
}

// =====================================================================
// shared 128x128 mainloop (8 warps 2m x 4n)
// =====================================================================
#define G128_MAINLOOP(FILLFN, NSTAGES, STAGEB, AOFFB)                            \
    for (int it = 0; it < KITER; ++it) {                                         \
        cp_wait<NSTAGES - 2>();                                                  \
        __syncthreads();                                                         \
        int fc = it + NSTAGES - 1;                                               \
        if (fc < KITER) FILLFN(sb + (fc % NSTAGES) * STAGEB, fc * 64, row0, j0, tid); \
        else cp_commit();                                                        \
        const uint32_t Ab = sb + (it % NSTAGES) * STAGEB;                        \
        const uint32_t Bb = Ab + AOFFB;                                          \
        _Pragma("unroll")                                                        \
        for (int kk = 0; kk < 4; kk++) {                                         \
            uint32_t a[4][4];                                                    \
            _Pragma("unroll")                                                    \
            for (int mi = 0; mi < 4; mi++)                                       \
                ldsm4(a[mi], Ab + (uint32_t)((wm * 64 + mi * 16 + lr) * 144 + (kk * 2 + lc) * 16)); \
            _Pragma("unroll")                                                    \
            for (int hh = 0; hh < 2; hh++) {                                     \
                uint32_t bb[4];                                                  \
                ldsm4(bb, Bb + (uint32_t)((wn * 32 + hh * 16 + lr) * 144 + (kk * 2 + lc) * 16)); \
                uint32_t b0[2] = {bb[0], bb[2]};                                 \
                uint32_t b1[2] = {bb[1], bb[3]};                                 \
                _Pragma("unroll")                                                \
                for (int mi = 0; mi < 4; mi++) {                                 \
                    mma16(acc[mi][hh * 2],     a[mi], b0);                       \
                    mma16(acc[mi][hh * 2 + 1], a[mi], b1);                       \
                }                                                                \
            }                                                                    \
        }                                                                        \
    }

// =====================================================================
// K_MB: M_b^T[j][cin] = sum_k (proj^T[j][k]*chw[b][k]) * Wv[cin][k]
// =====================================================================
#define MB_A 18432
#define MB_B 18432
#define MB_STAGE (MB_A + MB_B)
#define MB_NS 3

__device__ __forceinline__ void mb_fill(uint32_t sbase, int k0, int row0, int j0, int tid)
{
    #pragma unroll
    for (int i = 0; i < 4; i++) {
        int e = tid + i * 256;
        int r = e >> 3, c = e & 7;
        cp16(sbase + r * 144 + c * 16, g_pw2h + (size_t)(row0 + r) * 1024 + k0 + c * 8);
    }
    #pragma unroll
    for (int i = 0; i < 4; i++) {
        int e = tid + i * 256;
        int rr = e >> 3, c = e & 7;
        cp16(sbase + MB_A + rr * 144 + c * 16,
             g_wvh + (size_t)(j0 + rr) * 1024 + k0 + c * 8);
    }
    cp_commit();
}

__global__ __launch_bounds__(256, 2)
void k_mb()
{
    extern __shared__ __align__(128) char smem[];
    const uint32_t sb = smem_u32(smem);
    const int tid = threadIdx.x;
    const int wid = tid >> 5, lane = tid & 31;
    const int wm = wid & 1, wn = wid >> 1;
    const int grp = lane >> 2, qd = lane & 3;
    const int lr = lane & 15, lc = lane >> 4;
    const int j0 = blockIdx.x * 128;
    const int row0 = blockIdx.z * 1024 + blockIdx.y * 128;

    float acc[4][4][4];
    #pragma unroll
    for (int mi = 0; mi < 4; mi++)
        #pragma unroll
        for (int ni = 0; ni < 4; ni++)
            #pragma unroll
            for (int j = 0; j < 4; j++) acc[mi][ni][j] = 0.f;

    mb_fill(sb + 0 * MB_STAGE, 0,  row0, j0, tid);
    mb_fill(sb + 1 * MB_STAGE, 64, row0, j0, tid);

    G128_MAINLOOP(mb_fill, MB_NS, MB_STAGE, MB_A)

    #pragma unroll
    for (int mi = 0; mi < 4; mi++) {
        int rgl = row0 + wm * 64 + mi * 16 + grp;
        #pragma unroll
        for (int ni = 0; ni < 4; ni++) {
            int cg = j0 + wn * 32 + ni * 8 + qd * 2;
            *(__half2*)&g_mbh[(size_t)rgl * 1024 + cg] =
                __floats2half2_rn(acc[mi][ni][0], acc[mi][ni][1]);
            *(__half2*)&g_mbh[(size_t)(rgl + 8) * 1024 + cg] =
                __floats2half2_rn(acc[mi][ni][2], acc[mi][ni][3]);
        }
    }
}

// =====================================================================
// G2NW: y = x @ M_b (no softmax scaling — independent of qk/attn/ode)
// =====================================================================
#define G2_A 18432
#define G2_B 18432
#define G2_STAGE (G2_A + G2_B)
#define G2_NS 3

__device__ __forceinline__ void g2_fill(uint32_t sbase, int k0, int row0, int j0, int tid)
{
    const int b = row0 >> 11;
    #pragma unroll
    for (int i = 0; i < 4; i++) {
        int e = tid + i * 256;
        int r = e >> 3, c = e & 7;
        cp16(sbase + r * 144 + c * 16, g_xh + (size_t)(row0 + r) * 1024 + k0 + c * 8);
    }
    #pragma unroll
    for (int i = 0; i < 4; i++) {
        int e = tid + i * 256;
        int rr = e >> 3, c = e & 7;
        cp16(sbase + G2_A + rr * 144 + c * 16,
             g_mbh + ((size_t)b * 1024 + j0 + rr) * 1024 + k0 + c * 8);
    }
    cp_commit();
}

__global__ __launch_bounds__(256, 2)
void k_g2nw()
{
    extern __shared__ __align__(128) char smem[];
    const uint32_t sb = smem_u32(smem);
    const int tid = threadIdx.x;
    const int wid = tid >> 5, lane = tid & 31;
    const int wm = wid & 1, wn = wid >> 1;
    const int grp = lane >> 2, qd = lane & 3;
    const int lr = lane & 15, lc = lane >> 4;
    const int j0 = blockIdx.x * 128;
    const int row0 = blockIdx.y * 128;

    float acc[4][4][4];
    #pragma unroll
    for (int mi = 0; mi < 4; mi++)
        #pragma unroll
        for (int ni = 0; ni < 4; ni++)
            #pragma unroll
            for (int j = 0; j < 4; j++) acc[mi][ni][j] = 0.f;

    g2_fill(sb + 0 * G2_STAGE, 0,  row0, j0, tid);
    g2_fill(sb + 1 * G2_STAGE, 64, row0, j0, tid);

    G128_MAINLOOP(g2_fill, G2_NS, G2_STAGE, G2_A)

    // store fp32 y (exact)
    #pragma unroll
    for (int mi = 0; mi < 4; mi++) {
        int rgl = row0 + wm * 64 + mi * 16 + grp;
        #pragma unroll
        for (int ni = 0; ni < 4; ni++) {
            int cg = j0 + wn * 32 + ni * 8 + qd * 2;
            *(float2*)&g_y[(size_t)rgl * 1024 + cg] =
                make_float2(acc[mi][ni][0], acc[mi][ni][1]);
            *(float2*)&g_y[(size_t)(rgl + 8) * 1024 + cg] =
                make_float2(acc[mi][ni][2], acc[mi][ni][3]);
        }
    }
}

// =====================================================================
// epilogue: out = w[row] * y + bias   (HBM-bound, ~128 MB)
// =====================================================================
__global__ void k_epi(const float* __restrict__ pbias, float* __restrict__ out)
{
    size_t i = (size_t)blockIdx.x * 256 + threadIdx.x;   // float4 index
    int row = (int)(i >> 8);                             // 256 float4 per row
    int c4 = (int)(i & 255) * 4;
    float wr = g_w[row];
    float4 y = *((const float4*)g_y + i);
    float4 pb = *(const float4*)(pbias + c4);
    float4 o = {fmaf(y.x, wr, pb.x), fmaf(y.y, wr, pb.y),
                fmaf(y.z, wr, pb.z), fmaf(y.w, wr, pb.w)};
    *((float4*)out + i) = o;
}

// =====================================================================
// attn_base from stats
// =====================================================================
__global__ void k_attn(const float* __restrict__ c1p, const float* __restrict__ c2p)
{
    int row = blockIdx.x * 256 + threadIdx.x;
    float S0 = 0.f, S1 = 0.f, S2 = 0.f, S3 = 0.f, S4 = 0.f;
    #pragma unroll
    for (int p = 0; p < NPART; p++) {
        const float* d = g_stats + ((size_t)p * Mrows + row) * 5;
        S0 += d[0]; S1 += d[1]; S2 += d[2]; S3 += d[3]; S4 += d[4];
    }
    const float c1 = *c1p, c2 = *c2p;
    const float invC = 1.0f / (float)Cn;
    const float invcm1 = 1.0f / (float)(Cn - 1);
    float muq = S0 * invC, muk = S1 * invC;
    float sqk = (S4 - (float)Cn * muq * muk) * invcm1;
    float sq2 = (S2 - (float)Cn * muq * muq) * invcm1;
    float sk2 = (S3 - (float)Cn * muk * muk) * invcm1;
    float num = (2.f * muq * muk + c1) * (2.f * sqk + c2);
    float den = (muq * muq + muk * muk + c1) * (sq2 + sk2 + c2);
    float r = num / (den + 1e-7f);
    g_A[row] = r * r;
}

// =====================================================================
// ODE step + sigmoid + softmax over N
// =====================================================================
__device__ __forceinline__ float blk_sum(float v, float* red, int tid)
{
    red[tid] = v; __syncthreads();
    #pragma unroll
    for (int s = 128; s > 0; s >>= 1) {
        if (tid < s) red[tid] += red[tid + s];
        __syncthreads();
    }
    float r = red[0]; __syncthreads();
    return r;
}
__device__ __forceinline__ float blk_max(float v, float* red, int tid)
{
    red[tid] = v; __syncthreads();
    #pragma unroll
    for (int s = 128; s > 0; s >>= 1) {
        if (tid < s) red[tid] = fmaxf(red[tid], red[tid + s]);
        __syncthreads();
    }
    float r = red[0]; __syncthreads();
    return r;
}

__global__ __launch_bounds__(256)
void k_ode(const float* __restrict__ c1w, const float* __restrict__ gng,
           const float* __restrict__ gnb, const float* __restrict__ c2w,
           const float* __restrict__ c2b)
{
    const int b = blockIdx.x, tid = threadIdx.x;
    __shared__ float A[2048];
    __shared__ float h[4][2048];
    __shared__ float red[256];

    float w1[12], w2[12], gg[4], gb[4];
    #pragma unroll
    for (int t = 0; t < 12; t++) { w1[t] = c1w[t]; w2[t] = c2w[t]; }
    #pragma unroll
    for (int o = 0; o < 4; o++) { gg[o] = gng[o]; gb[o] = gnb[o]; }

    #pragma unroll
    for (int j = 0; j < 8; j++) { int n = tid + j * 256; A[n] = g_A[b * Nn + n]; }
    __syncthreads();

    float s0 = 0.f, ss0 = 0.f, s1 = 0.f, ss1 = 0.f;
    #pragma unroll
    for (int j = 0; j < 8; j++) {
        int n = tid + j * 256;
        float am = (n > 0)    ? A[n - 1] : 0.f;
        float a0 = A[n];
        float ap = (n < 2047) ? A[n + 1] : 0.f;
        #pragma unroll
        for (int o = 0; o < 4; o++) {
            float v = am * w1[o * 3] + a0 * w1[o * 3 + 1] + ap * w1[o * 3 + 2];
            h[o][n] = v;
            if (o < 2) { s0 += v; ss0 += v * v; } else { s1 += v; ss1 += v * v; }
        }
    }
    float S0  = blk_sum(s0,  red, tid);
    float SS0 = blk_sum(ss0, red, tid);
    float S1  = blk_sum(s1,  red, tid);
    float SS1 = blk_sum(ss1, red, tid);
    const float inv = 1.0f / 4096.0f;
    float mu[2] = {S0 * inv, S1 * inv};
    float rs[2] = {rsqrtf(SS0 * inv - mu[0] * mu[0] + 1e-5f),
                   rsqrtf(SS1 * inv - mu[1] * mu[1] + 1e-5f)};

    #pragma unroll
    for (int j = 0; j < 8; j++) {
        int n = tid + j * 256;
        #pragma unroll
        for (int o = 0; o < 4; o++) {
            int g = o >> 1;
            float v = (h[o][n] - mu[g]) * rs[g] * gg[o] + gb[o];
            h[o][n] = v > 0.f ? v : 0.f;
        }
    }
    __syncthreads();

    float fa[8];
    float c2bv = c2b[0];
    float mx = -1e30f;
    #pragma unroll
    for (int j = 0; j < 8; j++) {
        int n = tid + j * 256;
        float y = c2bv;
        #pragma unroll
        for (int o = 0; o < 4; o++) {
            float hm = (n > 0)    ? h[o][n - 1] : 0.f;
            float h0 = h[o][n];
            float hp = (n < 2047) ? h[o][n + 1] : 0.f;
            y += hm * w2[o * 3] + h0 * w2[o * 3 + 1] + hp * w2[o * 3 + 2];
        }
        float An = A[n] + y;
        float f = 1.0f / (1.0f + expf(-An));
        fa[j] = f;
        mx = fmaxf(mx, f);
    }

    float gmax = blk_max(mx, red, tid);
    float se = 0.f;
    #pragma unroll
    for (int j = 0; j < 8; j++) { fa[j] = expf(fa[j] - gmax); se += fa[j]; }
    float tot = blk_sum(se, red, tid);
    float invt = 1.0f / tot;
    #pragma unroll
    for (int j = 0; j < 8; j++) g_w[b * Nn + tid + j * 256] = fa[j] * invt;
}

// =====================================================================
// launch — fork/join graph; gemm2 mainloop decoupled from w.
// origin: mean_prep -> qk -> attn -> ode -> [join y] -> epi
// s1: prep_w -> (e_w) -> prep_wv -> prep_pwT -> [e_ch] scale_pw -> mb -> g2nw
// s2: chm -> ch1 -> ch2
// =====================================================================
extern "C" void kernel_launch(void* const* d_in, const int* in_sizes, int n_in,
                              void* d_out, int out_size)
{
    const float* x       = (const float*)d_in[0];
    const float* qkv_w   = (const float*)d_in[1];
    const float* c1      = (const float*)d_in[2];
    const float* c2      = (const float*)d_in[3];
    const float* conv1_w = (const float*)d_in[4];
    const float* gn_g    = (const float*)d_in[5];
    const float* gn_b    = (const float*)d_in[6];
    const float* conv2_w = (const float*)d_in[7];
    const float* conv2_b = (const float*)d_in[8];
    const float* ch_w1   = (const float*)d_in[9];
    const float* ch_b1   = (const float*)d_in[10];
    const float* ch_w2   = (const float*)d_in[11];
    const float* ch_b2   = (const float*)d_in[12];
    const float* proj_w  = (const float*)d_in[13];
    const float* proj_b  = (const float*)d_in[14];
    float* out = (float*)d_out;

    static cudaStream_t s1 = nullptr, s2 = nullptr;
    static cudaEvent_t e_root, e_m, e_w, e_ch, e_y;
    if (s1 == nullptr) {
        cudaStreamCreateWithFlags(&s1, cudaStreamNonBlocking);
        cudaStreamCreateWithFlags(&s2, cudaStreamNonBlocking);
        cudaEventCreateWithFlags(&e_root, cudaEventDisableTiming);
        cudaEventCreateWithFlags(&e_m,    cudaEventDisableTiming);
        cudaEventCreateWithFlags(&e_w,    cudaEventDisableTiming);
        cudaEventCreateWithFlags(&e_ch,   cudaEventDisableTiming);
        cudaEventCreateWithFlags(&e_y,    cudaEventDisableTiming);
        cudaFuncSetAttribute(k_gemm_qk, cudaFuncAttributeMaxDynamicSharedMemorySize, QK_NS * QK_STAGE);
        cudaFuncSetAttribute(k_mb,      cudaFuncAttributeMaxDynamicSharedMemorySize, MB_NS * MB_STAGE);
        cudaFuncSetAttribute(k_g2nw,    cudaFuncAttributeMaxDynamicSharedMemorySize, G2_NS * G2_STAGE);
    }

    // ---- fork s1 from origin ----
    cudaEventRecord(e_root, 0);
    cudaStreamWaitEvent(s1, e_root, 0);

    // origin: x -> fp16 + mean partials
    k_mean_prep<<<dim3(64, 8), 1024, 0, 0>>>(x);
    cudaEventRecord(e_m, 0);
    cudaStreamWaitEvent(s2, e_m, 0);            // fork s2 after mean_prep

    // s1: weight preps
    k_prep_w  <<<dim3(64, 32), dim3(32, 8), 0, s1>>>(qkv_w);
    cudaEventRecord(e_w, s1);
    k_prep_wv <<<1024, 256, 0, s1>>>(qkv_w);
    k_prep_pwT<<<dim3(32, 32), dim3(32, 8), 0, s1>>>(proj_w);

    // s2: channel gate chain
    k_chm<<<8, 1024, 0, s2>>>();
    k_ch1<<<dim3(32, 8), 256, 0, s2>>>(ch_w1, ch_b1);
    k_ch2<<<dim3(128, 8), 256, 0, s2>>>(ch_w2, ch_b2);
    cudaEventRecord(e_ch, s2);

    // s1: chw-scaled proj copies, M_b build, then the w-independent y = x@M_b
    cudaStreamWaitEvent(s1, e_ch, 0);
    k_scale_pw<<<dim3(1024, 8), 256, 0, s1>>>();
    k_mb  <<<dim3(8, 8, 8), 256, MB_NS * MB_STAGE, s1>>>();
    k_g2nw<<<dim3(8, 128), 256, G2_NS * G2_STAGE, s1>>>();
    cudaEventRecord(e_y, s1);

    // origin: big QK gemm, then attn + ode (softmax weights)
    cudaStreamWaitEvent(0, e_w, 0);
    k_gemm_qk<<<dim3(16, 128), 256, QK_NS * QK_STAGE, 0>>>();
    k_attn<<<64, 256, 0, 0>>>(c1, c2);
    k_ode <<<8, 256, 0, 0>>>(conv1_w, gn_g, gn_b, conv2_w, conv2_b);

    // join y, final elementwise epilogue
    cudaStreamWaitEvent(0, e_y, 0);
    k_epi<<<16384, 256, 0, 0>>>(proj_b, out);
}

// round 16
// speedup vs baseline: 1.0464x; 1.0464x over previous
#include <cuda_runtime.h>
#include <cuda_fp16.h>
#include <math.h>
#include <stdint.h>

// Problem constants
#define Bn 8
#define Nn 2048
#define Cn 1024
#define Mrows (Bn*Nn)   // 16384
#define NPART 32        // stats partials: 16 j-tiles x 2 warp-columns
#define MCHUNK 64       // mean partial chunks (32 rows each)

// ---------------- scratch (device globals) ----------------
__device__ __half g_xh[(size_t)Mrows * Cn];            // 32 MB: fp16(x)
__device__ __half g_wth[(size_t)2048 * 1024];          // 4 MB: fp16([Wq,Wk]^T) [j][k]
__device__ __half g_wvh[(size_t)1024 * 1024];          // 2 MB: fp16(Wv) [cin][cout]
__device__ __half g_pwh[(size_t)1024 * 1024];          // 2 MB: fp16(proj_w^T) [j][k]
__device__ __half g_pw2h[(size_t)Bn * 1024 * 1024];    // 16 MB: fp16(proj^T * chw[b])
__device__ __half g_mbh[(size_t)Bn * 1024 * 1024];     // 16 MB: fp16(M_b^T[j][cin])
__device__ float g_stats[(size_t)NPART * Mrows * 5];
__device__ float g_mpart[MCHUNK * Bn * Cn];
__device__ float g_m[Bn * Cn];
__device__ float g_h[Bn * 256];
__device__ float g_A[Mrows];
__device__ float g_w[Mrows];
__device__ float g_chw[Bn * Cn];

// ---------------- helpers ----------------
__device__ __forceinline__ uint32_t smem_u32(const void* p) {
    uint32_t a;
    asm("{ .reg .u64 t; cvta.to.shared.u64 t, %1; cvt.u32.u64 %0, t; }" : "=r"(a) : "l"(p));
    return a;
}
__device__ __forceinline__ void cp16(uint32_t dst, const void* src) {
    asm volatile("cp.async.cg.shared.global [%0], [%1], 16;" :: "r"(dst), "l"(src));
}
__device__ __forceinline__ void cp_commit() { asm volatile("cp.async.commit_group;" ::: "memory"); }
template<int N> __device__ __forceinline__ void cp_wait() {
    asm volatile("cp.async.wait_group %0;" :: "n"(N) : "memory");
}
__device__ __forceinline__ void ldsm4(uint32_t* r, uint32_t a) {
    asm volatile("ldmatrix.sync.aligned.m8n8.x4.shared.b16 {%0,%1,%2,%3}, [%4];"
                 : "=r"(r[0]), "=r"(r[1]), "=r"(r[2]), "=r"(r[3]) : "r"(a));
}
__device__ __forceinline__ void mma16(float* d, const uint32_t* a, const uint32_t* b) {
    asm volatile(
        "mma.sync.aligned.m16n8k16.row.col.f32.f16.f16.f32 "
        "{%0,%1,%2,%3}, {%4,%5,%6,%7}, {%8,%9}, {%0,%1,%2,%3};"
        : "+f"(d[0]), "+f"(d[1]), "+f"(d[2]), "+f"(d[3])
        : "r"(a[0]), "r"(a[1]), "r"(a[2]), "r"(a[3]), "r"(b[0]), "r"(b[1]));
}
__device__ __forceinline__ float warp_sum(float v) {
    #pragma unroll
    for (int off = 16; off > 0; off >>= 1)
        v += __shfl_xor_sync(0xffffffffu, v, off);
    return v;
}

// =====================================================================
// fused: column-sum partials of x over n (32-row chunks) + fp16 conversion
// grid (64, 8) x 1024 threads — 512 CTAs, all SMs engaged
// =====================================================================
__global__ void k_mean_prep(const float* __restrict__ x)
{
    int p = blockIdx.x, b = blockIdx.y, c = threadIdx.x;
    const size_t base = ((size_t)b * Nn + p * 32) * Cn + c;
    float s = 0.f;
    #pragma unroll 4
    for (int n = 0; n < 32; n++) {
        float v = x[base + (size_t)n * Cn];
        s += v;
        g_xh[base + (size_t)n * Cn] = __float2half_rn(v);
    }
    g_mpart[(p * Bn + b) * Cn + c] = s;
}

// =====================================================================
// weight preps
// =====================================================================
__global__ void k_prep_w(const float* __restrict__ w) {   // qkv_w cols 0..2047 -> g_wth[2048][1024]
    __shared__ float t[32][33];
    int j0 = blockIdx.x * 32, k0 = blockIdx.y * 32;
    int tx = threadIdx.x, ty = threadIdx.y;
    #pragma unroll
    for (int l = 0; l < 4; l++)
        t[ty + l * 8][tx] = w[(size_t)(k0 + ty + l * 8) * 3072 + j0 + tx];
    __syncthreads();
    #pragma unroll
    for (int l = 0; l < 4; l++)
        g_wth[(size_t)(j0 + ty + l * 8) * 1024 + k0 + tx] = __float2half_rn(t[tx][ty + l * 8]);
}
__global__ void k_prep_wv(const float* __restrict__ w) {  // qkv_w cols 2048.. -> g_wvh[cin][cout]
    int cin = blockIdx.x;
    int c4 = threadIdx.x * 4;
    float4 v = *(const float4*)(w + (size_t)cin * 3072 + 2048 + c4);
    *(__half2*)(g_wvh + (size_t)cin * 1024 + c4)     = __floats2half2_rn(v.x, v.y);
    *(__half2*)(g_wvh + (size_t)cin * 1024 + c4 + 2) = __floats2half2_rn(v.z, v.w);
}
__global__ void k_prep_pwT(const float* __restrict__ pw) { // [1024][1024] -> g_pwh[j][k]
    __shared__ float t[32][33];
    int j0 = blockIdx.x * 32, k0 = blockIdx.y * 32;
    int tx = threadIdx.x, ty = threadIdx.y;
    #pragma unroll
    for (int l = 0; l < 4; l++)
        t[ty + l * 8][tx] = pw[(size_t)(k0 + ty + l * 8) * 1024 + j0 + tx];
    __syncthreads();
    #pragma unroll
    for (int l = 0; l < 4; l++)
        g_pwh[(size_t)(j0 + ty + l * 8) * 1024 + k0 + tx] = __float2half_rn(t[tx][ty + l * 8]);
}
// g_pw2h[b][j][k] = g_pwh[j][k] * chw[b][k]
__global__ void k_scale_pw()
{
    int j = blockIdx.x, b = blockIdx.y;
    int k4 = threadIdx.x * 4;
    __half2 p0 = *(__half2*)(g_pwh + (size_t)j * 1024 + k4);
    __half2 p1 = *(__half2*)(g_pwh + (size_t)j * 1024 + k4 + 2);
    float4 cw = *(const float4*)(g_chw + b * Cn + k4);
    float2 f0 = __half22float2(p0);
    float2 f1 = __half22float2(p1);
    __half* dst = g_pw2h + ((size_t)b * 1024 + j) * 1024 + k4;
    *(__half2*)dst       = __floats2half2_rn(f0.x * cw.x, f0.y * cw.y);
    *(__half2*)(dst + 2) = __floats2half2_rn(f1.x * cw.z, f1.y * cw.w);
}

// =====================================================================
// channel gate
// =====================================================================
__global__ void k_chm()
{
    int b = blockIdx.x, c = threadIdx.x;
    float s = 0.f;
    #pragma unroll
    for (int p = 0; p < MCHUNK; p++) s += g_mpart[(p * Bn + b) * Cn + c];
    g_m[b * Cn + c] = s * (1.0f / (float)Nn);
}

__global__ __launch_bounds__(256)
void k_ch1(const float* __restrict__ w1, const float* __restrict__ b1)
{
    const int b = blockIdx.y;
    const int j = blockIdx.x * 8 + (threadIdx.x >> 5);
    const int lane = threadIdx.x & 31;
    float s = 0.f;
    #pragma unroll 8
    for (int i = 0; i < 32; i++) {
        int c = lane + i * 32;
        s = fmaf(g_m[b * Cn + c], w1[c * 256 + j], s);
    }
    s = warp_sum(s);
    if (lane == 0) g_h[b * 256 + j] = fmaxf(s + b1[j], 0.f);
}

__global__ __launch_bounds__(256)
void k_ch2(const float* __restrict__ w2, const float* __restrict__ b2)
{
    const int b = blockIdx.y;
    const int c = blockIdx.x * 8 + (threadIdx.x >> 5);
    const int lane = threadIdx.x & 31;
    float s = 0.f;
    #pragma unroll
    for (int i = 0; i < 8; i++) {
        int j = lane + i * 32;
        s = fmaf(g_h[b * 256 + j], w2[j * 1024 + c], s);
    }
    s = warp_sum(s);
    if (lane == 0) g_chw[b * Cn + c] = 1.0f / (1.0f + expf(-(s + b2[c])));
}

// =====================================================================
// GEMM-QK (fp16 mma.sync): q,k = x @ [Wq,Wk]; stats only
//  block 128m x 64n x {q,k}, k-chunk 64, 3 stages, 8 warps (4m x 2n), 2 CTAs/SM
// =====================================================================
#define QK_A 18432
#define QK_B 9216
#define QK_STAGE (QK_A + 2*QK_B)   // 36864
#define QK_NS 3
#define KITER 16

__device__ __forceinline__ void qk_fill(uint32_t sbase, int k0, int row0, int j0, int tid)
{
    #pragma unroll
    for (int i = 0; i < 4; i++) {
        int e = tid + i * 256;
        int r = e >> 3, c = e & 7;
        cp16(sbase + r * 144 + c * 16, g_xh + (size_t)(row0 + r) * 1024 + k0 + c * 8);
    }
    #pragma unroll
    for (int i = 0; i < 4; i++) {
        int e = tid + i * 256;
        int t = e >> 9, rr = (e >> 3) & 63, c = e & 7;
        cp16(sbase + QK_A + t * QK_B + rr * 144 + c * 16,
             g_wth + (size_t)(t * 1024 + j0 + rr) * 1024 + k0 + c * 8);
    }
    cp_commit();
}

__global__ __launch_bounds__(256, 2)
void k_gemm_qk()
{
    extern __shared__ __align__(128) char smem[];
    const uint32_t sb = smem_u32(smem);
    const int tid = threadIdx.x;
    const int wid = tid >> 5, lane = tid & 31;
    const int wm = wid & 3, wn = wid >> 2;
    const int grp = lane >> 2, qd = lane & 3;
    const int lr = lane & 15, lc = lane >> 4;
    const int j0 = blockIdx.x * 64;
    const int row0 = blockIdx.y * 128;

    float acc[2][2][4][4];
    #pragma unroll
    for (int t = 0; t < 2; t++)
        #pragma unroll
        for (int mi = 0; mi < 2; mi++)
            #pragma unroll
            for (int ni = 0; ni < 4; ni++)
                #pragma unroll
                for (int j = 0; j < 4; j++) acc[t][mi][ni][j] = 0.f;

    qk_fill(sb + 0 * QK_STAGE, 0,  row0, j0, tid);
    qk_fill(sb + 1 * QK_STAGE, 64, row0, j0, tid);

    for (int it = 0; it < KITER; ++it) {
        cp_wait<QK_NS - 2>();
        __syncthreads();
        int fc = it + QK_NS - 1;
        if (fc < KITER) qk_fill(sb + (fc % QK_NS) * QK_STAGE, fc * 64, row0, j0, tid);
        else cp_commit();

        const uint32_t Ab = sb + (it % QK_NS) * QK_STAGE;
        const uint32_t Bb = Ab + QK_A;
        #pragma unroll
        for (int kk = 0; kk < 4; kk++) {
            uint32_t a[2][4];
            #pragma unroll
            for (int mi = 0; mi < 2; mi++)
                ldsm4(a[mi], Ab + (uint32_t)((wm * 32 + mi * 16 + lr) * 144 + (kk * 2 + lc) * 16));
            #pragma unroll
            for (int t = 0; t < 2; t++) {
                #pragma unroll
                for (int hh = 0; hh < 2; hh++) {
                    uint32_t bb[4];
                    ldsm4(bb, Bb + (uint32_t)(t * QK_B + (wn * 32 + hh * 16 + lr) * 144 + (kk * 2 + lc) * 16));
                    uint32_t b0[2] = {bb[0], bb[2]};
                    uint32_t b1[2] = {bb[1], bb[3]};
                    #pragma unroll
                    for (int mi = 0; mi < 2; mi++) {
                        mma16(acc[t][mi][hh * 2],     a[mi], b0);
                        mma16(acc[t][mi][hh * 2 + 1], a[mi], b1);
                    }
                }
            }
        }
    }

    const int p = blockIdx.x * 2 + wn;
    #pragma unroll
    for (int mi = 0; mi < 2; mi++) {
        #pragma unroll
        for (int h = 0; h < 2; h++) {
            float sq = 0.f, sk = 0.f, sqq = 0.f, skk = 0.f, sqk = 0.f;
            #pragma unroll
            for (int ni = 0; ni < 4; ni++) {
                #pragma unroll
                for (int j = 0; j < 2; j++) {
                    float q = acc[0][mi][ni][h * 2 + j];
                    float k = acc[1][mi][ni][h * 2 + j];
                    sq += q; sk += k; sqq += q * q; skk += k * k; sqk += q * k;
                }
            }
            #pragma unroll
            for (int off = 1; off <= 2; off <<= 1) {
                sq  += __shfl_xor_sync(0xffffffffu, sq,  off);
                sk  += __shfl_xor_sync(0xffffffffu, sk,  off);
                sqq += __shfl_xor_sync(0xffffffffu, sqq, off);
                skk += __shfl_xor_sync(0xffffffffu, skk, off);
                sqk += __shfl_xor_sync(0xffffffffu, sqk, off);
            }
            if (qd == 0) {
                int row = row0 + wm * 32 + mi * 16 + grp + h * 8;
                float* d = g_stats + ((size_t)p * Mrows + row) * 5;
                d[0] = sq; d[1] = sk; d[2] = sqq; d[3] = skk; d[4] = sqk;
            }
        }
    }
}

// =====================================================================
// shared 128x128 mainloop (8 warps 2m x 4n)
// =====================================================================
#define G128_MAINLOOP(FILLFN, NSTAGES, STAGEB, AOFFB)                            \
    for (int it = 0; it < KITER; ++it) {                                         \
        cp_wait<NSTAGES - 2>();                                                  \
        __syncthreads();                                                         \
        int fc = it + NSTAGES - 1;                                               \
        if (fc < KITER) FILLFN(sb + (fc % NSTAGES) * STAGEB, fc * 64, row0, j0, tid); \
        else cp_commit();                                                        \
        const uint32_t Ab = sb + (it % NSTAGES) * STAGEB;                        \
        const uint32_t Bb = Ab + AOFFB;                                          \
        _Pragma("unroll")                                                        \
        for (int kk = 0; kk < 4; kk++) {                                         \
            uint32_t a[4][4];                                                    \
            _Pragma("unroll")                                                    \
            for (int mi = 0; mi < 4; mi++)                                       \
                ldsm4(a[mi], Ab + (uint32_t)((wm * 64 + mi * 16 + lr) * 144 + (kk * 2 + lc) * 16)); \
            _Pragma("unroll")                                                    \
            for (int hh = 0; hh < 2; hh++) {                                     \
                uint32_t bb[4];                                                  \
                ldsm4(bb, Bb + (uint32_t)((wn * 32 + hh * 16 + lr) * 144 + (kk * 2 + lc) * 16)); \
                uint32_t b0[2] = {bb[0], bb[2]};                                 \
                uint32_t b1[2] = {bb[1], bb[3]};                                 \
                _Pragma("unroll")                                                \
                for (int mi = 0; mi < 4; mi++) {                                 \
                    mma16(acc[mi][hh * 2],     a[mi], b0);                       \
                    mma16(acc[mi][hh * 2 + 1], a[mi], b1);                       \
                }                                                                \
            }                                                                    \
        }                                                                        \
    }

// =====================================================================
// K_MB: M_b^T[j][cin] = sum_k (proj^T[j][k]*chw[b][k]) * Wv[cin][k]
// =====================================================================
#define MB_A 18432
#define MB_B 18432
#define MB_STAGE (MB_A + MB_B)
#define MB_NS 3

__device__ __forceinline__ void mb_fill(uint32_t sbase, int k0, int row0, int j0, int tid)
{
    #pragma unroll
    for (int i = 0; i < 4; i++) {
        int e = tid + i * 256;
        int r = e >> 3, c = e & 7;
        cp16(sbase + r * 144 + c * 16, g_pw2h + (size_t)(row0 + r) * 1024 + k0 + c * 8);
    }
    #pragma unroll
    for (int i = 0; i < 4; i++) {
        int e = tid + i * 256;
        int rr = e >> 3, c = e & 7;
        cp16(sbase + MB_A + rr * 144 + c * 16,
             g_wvh + (size_t)(j0 + rr) * 1024 + k0 + c * 8);
    }
    cp_commit();
}

__global__ __launch_bounds__(256, 2)
void k_mb()
{
    extern __shared__ __align__(128) char smem[];
    const uint32_t sb = smem_u32(smem);
    const int tid = threadIdx.x;
    const int wid = tid >> 5, lane = tid & 31;
    const int wm = wid & 1, wn = wid >> 1;
    const int grp = lane >> 2, qd = lane & 3;
    const int lr = lane & 15, lc = lane >> 4;
    const int j0 = blockIdx.x * 128;
    const int row0 = blockIdx.z * 1024 + blockIdx.y * 128;

    float acc[4][4][4];
    #pragma unroll
    for (int mi = 0; mi < 4; mi++)
        #pragma unroll
        for (int ni = 0; ni < 4; ni++)
            #pragma unroll
            for (int j = 0; j < 4; j++) acc[mi][ni][j] = 0.f;

    mb_fill(sb + 0 * MB_STAGE, 0,  row0, j0, tid);
    mb_fill(sb + 1 * MB_STAGE, 64, row0, j0, tid);

    G128_MAINLOOP(mb_fill, MB_NS, MB_STAGE, MB_A)

    #pragma unroll
    for (int mi = 0; mi < 4; mi++) {
        int rgl = row0 + wm * 64 + mi * 16 + grp;
        #pragma unroll
        for (int ni = 0; ni < 4; ni++) {
            int cg = j0 + wn * 32 + ni * 8 + qd * 2;
            *(__half2*)&g_mbh[(size_t)rgl * 1024 + cg] =
                __floats2half2_rn(acc[mi][ni][0], acc[mi][ni][1]);
            *(__half2*)&g_mbh[(size_t)(rgl + 8) * 1024 + cg] =
                __floats2half2_rn(acc[mi][ni][2], acc[mi][ni][3]);
        }
    }
}

// =====================================================================
// GEMM2: out = diag(w_softmax) * (x @ M_b) + bias
// =====================================================================
#define G2_A 18432
#define G2_B 18432
#define G2_STAGE (G2_A + G2_B)
#define G2_NS 3

__device__ __forceinline__ void g2_fill(uint32_t sbase, int k0, int row0, int j0, int tid)
{
    const int b = row0 >> 11;
    #pragma unroll
    for (int i = 0; i < 4; i++) {
        int e = tid + i * 256;
        int r = e >> 3, c = e & 7;
        cp16(sbase + r * 144 + c * 16, g_xh + (size_t)(row0 + r) * 1024 + k0 + c * 8);
    }
    #pragma unroll
    for (int i = 0; i < 4; i++) {
        int e = tid + i * 256;
        int rr = e >> 3, c = e & 7;
        cp16(sbase + G2_A + rr * 144 + c * 16,
             g_mbh + ((size_t)b * 1024 + j0 + rr) * 1024 + k0 + c * 8);
    }
    cp_commit();
}

__global__ __launch_bounds__(256, 2)
void k_gemm2(const float* __restrict__ pbias, float* __restrict__ out)
{
    extern __shared__ __align__(128) char smem[];
    const uint32_t sb = smem_u32(smem);
    const int tid = threadIdx.x;
    const int wid = tid >> 5, lane = tid & 31;
    const int wm = wid & 1, wn = wid >> 1;
    const int grp = lane >> 2, qd = lane & 3;
    const int lr = lane & 15, lc = lane >> 4;
    const int j0 = blockIdx.x * 128;
    const int row0 = blockIdx.y * 128;

    float acc[4][4][4];
    #pragma unroll
    for (int mi = 0; mi < 4; mi++)
        #pragma unroll
        for (int ni = 0; ni < 4; ni++)
            #pragma unroll
            for (int j = 0; j < 4; j++) acc[mi][ni][j] = 0.f;

    g2_fill(sb + 0 * G2_STAGE, 0,  row0, j0, tid);
    g2_fill(sb + 1 * G2_STAGE, 64, row0, j0, tid);

    G128_MAINLOOP(g2_fill, G2_NS, G2_STAGE, G2_A)

    #pragma unroll
    for (int mi = 0; mi < 4; mi++) {
        int rgl = row0 + wm * 64 + mi * 16 + grp;
        float wrl = g_w[rgl];
        float wrh = g_w[rgl + 8];
        #pragma unroll
        for (int ni = 0; ni < 4; ni++) {
            int cg = j0 + wn * 32 + ni * 8 + qd * 2;
            float2 pb2 = *(const float2*)(pbias + cg);
            float2 lo = {acc[mi][ni][0] * wrl + pb2.x, acc[mi][ni][1] * wrl + pb2.y};
            float2 hi = {acc[mi][ni][2] * wrh + pb2.x, acc[mi][ni][3] * wrh + pb2.y};
            *(float2*)&out[(size_t)rgl * 1024 + cg] = lo;
            *(float2*)&out[(size_t)(rgl + 8) * 1024 + cg] = hi;
        }
    }
}

// =====================================================================
// attn_base from stats
// =====================================================================
__global__ void k_attn(const float* __restrict__ c1p, const float* __restrict__ c2p)
{
    int row = blockIdx.x * 256 + threadIdx.x;
    float S0 = 0.f, S1 = 0.f, S2 = 0.f, S3 = 0.f, S4 = 0.f;
    #pragma unroll
    for (int p = 0; p < NPART; p++) {
        const float* d = g_stats + ((size_t)p * Mrows + row) * 5;
        S0 += d[0]; S1 += d[1]; S2 += d[2]; S3 += d[3]; S4 += d[4];
    }
    const float c1 = *c1p, c2 = *c2p;
    const float invC = 1.0f / (float)Cn;
    const float invcm1 = 1.0f / (float)(Cn - 1);
    float muq = S0 * invC, muk = S1 * invC;
    float sqk = (S4 - (float)Cn * muq * muk) * invcm1;
    float sq2 = (S2 - (float)Cn * muq * muq) * invcm1;
    float sk2 = (S3 - (float)Cn * muk * muk) * invcm1;
    float num = (2.f * muq * muk + c1) * (2.f * sqk + c2);
    float den = (muq * muq + muk * muk + c1) * (sq2 + sk2 + c2);
    float r = num / (den + 1e-7f);
    g_A[row] = r * r;
}

// =====================================================================
// ODE step + sigmoid + softmax over N
// =====================================================================
__device__ __forceinline__ float blk_sum(float v, float* red, int tid)
{
    red[tid] = v; __syncthreads();
    #pragma unroll
    for (int s = 128; s > 0; s >>= 1) {
        if (tid < s) red[tid] += red[tid + s];
        __syncthreads();
    }
    float r = red[0]; __syncthreads();
    return r;
}
__device__ __forceinline__ float blk_max(float v, float* red, int tid)
{
    red[tid] = v; __syncthreads();
    #pragma unroll
    for (int s = 128; s > 0; s >>= 1) {
        if (tid < s) red[tid] = fmaxf(red[tid], red[tid + s]);
        __syncthreads();
    }
    float r = red[0]; __syncthreads();
    return r;
}

__global__ __launch_bounds__(256)
void k_ode(const float* __restrict__ c1w, const float* __restrict__ gng,
           const float* __restrict__ gnb, const float* __restrict__ c2w,
           const float* __restrict__ c2b)
{
    const int b = blockIdx.x, tid = threadIdx.x;
    __shared__ float A[2048];
    __shared__ float h[4][2048];
    __shared__ float red[256];

    float w1[12], w2[12], gg[4], gb[4];
    #pragma unroll
    for (int t = 0; t < 12; t++) { w1[t] = c1w[t]; w2[t] = c2w[t]; }
    #pragma unroll
    for (int o = 0; o < 4; o++) { gg[o] = gng[o]; gb[o] = gnb[o]; }

    #pragma unroll
    for (int j = 0; j < 8; j++) { int n = tid + j * 256; A[n] = g_A[b * Nn + n]; }
    __syncthreads();

    float s0 = 0.f, ss0 = 0.f, s1 = 0.f, ss1 = 0.f;
    #pragma unroll
    for (int j = 0; j < 8; j++) {
        int n = tid + j * 256;
        float am = (n > 0)    ? A[n - 1] : 0.f;
        float a0 = A[n];
        float ap = (n < 2047) ? A[n + 1] : 0.f;
        #pragma unroll
        for (int o = 0; o < 4; o++) {
            float v = am * w1[o * 3] + a0 * w1[o * 3 + 1] + ap * w1[o * 3 + 2];
            h[o][n] = v;
            if (o < 2) { s0 += v; ss0 += v * v; } else { s1 += v; ss1 += v * v; }
        }
    }
    float S0  = blk_sum(s0,  red, tid);
    float SS0 = blk_sum(ss0, red, tid);
    float S1  = blk_sum(s1,  red, tid);
    float SS1 = blk_sum(ss1, red, tid);
    const float inv = 1.0f / 4096.0f;
    float mu[2] = {S0 * inv, S1 * inv};
    float rs[2] = {rsqrtf(SS0 * inv - mu[0] * mu[0] + 1e-5f),
                   rsqrtf(SS1 * inv - mu[1] * mu[1] + 1e-5f)};

    #pragma unroll
    for (int j = 0; j < 8; j++) {
        int n = tid + j * 256;
        #pragma unroll
        for (int o = 0; o < 4; o++) {
            int g = o >> 1;
            float v = (h[o][n] - mu[g]) * rs[g] * gg[o] + gb[o];
            h[o][n] = v > 0.f ? v : 0.f;
        }
    }
    __syncthreads();

    float fa[8];
    float c2bv = c2b[0];
    float mx = -1e30f;
    #pragma unroll
    for (int j = 0; j < 8; j++) {
        int n = tid + j * 256;
        float y = c2bv;
        #pragma unroll
        for (int o = 0; o < 4; o++) {
            float hm = (n > 0)    ? h[o][n - 1] : 0.f;
            float h0 = h[o][n];
            float hp = (n < 2047) ? h[o][n + 1] : 0.f;
            y += hm * w2[o * 3] + h0 * w2[o * 3 + 1] + hp * w2[o * 3 + 2];
        }
        float An = A[n] + y;
        float f = 1.0f / (1.0f + expf(-An));
        fa[j] = f;
        mx = fmaxf(mx, f);
    }

    float gmax = blk_max(mx, red, tid);
    float se = 0.f;
    #pragma unroll
    for (int j = 0; j < 8; j++) { fa[j] = expf(fa[j] - gmax); se += fa[j]; }
    float tot = blk_sum(se, red, tid);
    float invt = 1.0f / tot;
    #pragma unroll
    for (int j = 0; j < 8; j++) g_w[b * Nn + tid + j * 256] = fa[j] * invt;
}

// =====================================================================
// launch — R14 schedule (best measured: 442.4 us), fork/join graph.
// origin: mean_prep -> qk -> attn -> ode -> [join mb] -> gemm2
// s1: prep_w -> (e_w) -> prep_wv -> prep_pwT -> [e_ch] scale_pw -> mb
// s2: chm -> ch1 -> ch2
// =====================================================================
extern "C" void kernel_launch(void* const* d_in, const int* in_sizes, int n_in,
                              void* d_out, int out_size)
{
    const float* x       = (const float*)d_in[0];
    const float* qkv_w   = (const float*)d_in[1];
    const float* c1      = (const float*)d_in[2];
    const float* c2      = (const float*)d_in[3];
    const float* conv1_w = (const float*)d_in[4];
    const float* gn_g    = (const float*)d_in[5];
    const float* gn_b    = (const float*)d_in[6];
    const float* conv2_w = (const float*)d_in[7];
    const float* conv2_b = (const float*)d_in[8];
    const float* ch_w1   = (const float*)d_in[9];
    const float* ch_b1   = (const float*)d_in[10];
    const float* ch_w2   = (const float*)d_in[11];
    const float* ch_b2   = (const float*)d_in[12];
    const float* proj_w  = (const float*)d_in[13];
    const float* proj_b  = (const float*)d_in[14];
    float* out = (float*)d_out;

    static cudaStream_t s1 = nullptr, s2 = nullptr;
    static cudaEvent_t e_root, e_m, e_w, e_ch, e_mb;
    if (s1 == nullptr) {
        cudaStreamCreateWithFlags(&s1, cudaStreamNonBlocking);
        cudaStreamCreateWithFlags(&s2, cudaStreamNonBlocking);
        cudaEventCreateWithFlags(&e_root, cudaEventDisableTiming);
        cudaEventCreateWithFlags(&e_m,    cudaEventDisableTiming);
        cudaEventCreateWithFlags(&e_w,    cudaEventDisableTiming);
        cudaEventCreateWithFlags(&e_ch,   cudaEventDisableTiming);
        cudaEventCreateWithFlags(&e_mb,   cudaEventDisableTiming);
        cudaFuncSetAttribute(k_gemm_qk, cudaFuncAttributeMaxDynamicSharedMemorySize, QK_NS * QK_STAGE);
        cudaFuncSetAttribute(k_mb,      cudaFuncAttributeMaxDynamicSharedMemorySize, MB_NS * MB_STAGE);
        cudaFuncSetAttribute(k_gemm2,   cudaFuncAttributeMaxDynamicSharedMemorySize, G2_NS * G2_STAGE);
    }

    // ---- fork s1 from origin ----
    cudaEventRecord(e_root, 0);
    cudaStreamWaitEvent(s1, e_root, 0);

    // origin: x -> fp16 + mean partials (512 CTAs)
    k_mean_prep<<<dim3(64, 8), 1024, 0, 0>>>(x);
    cudaEventRecord(e_m, 0);
    cudaStreamWaitEvent(s2, e_m, 0);            // fork s2 after mean_prep

    // s1: weight preps; e_w right after prep_w so qk starts ASAP
    k_prep_w  <<<dim3(64, 32), dim3(32, 8), 0, s1>>>(qkv_w);
    cudaEventRecord(e_w, s1);
    k_prep_wv <<<1024, 256, 0, s1>>>(qkv_w);
    k_prep_pwT<<<dim3(32, 32), dim3(32, 8), 0, s1>>>(proj_w);

    // s2: channel gate chain
    k_chm<<<8, 1024, 0, s2>>>();
    k_ch1<<<dim3(32, 8), 256, 0, s2>>>(ch_w1, ch_b1);
    k_ch2<<<dim3(128, 8), 256, 0, s2>>>(ch_w2, ch_b2);
    cudaEventRecord(e_ch, s2);

    // s1: chw-scaled proj copies, then M_b build (runs || qk)
    cudaStreamWaitEvent(s1, e_ch, 0);
    k_scale_pw<<<dim3(1024, 8), 256, 0, s1>>>();
    k_mb<<<dim3(8, 8, 8), 256, MB_NS * MB_STAGE, s1>>>();
    cudaEventRecord(e_mb, s1);

    // origin: big QK gemm (needs wth), then attn + ode
    cudaStreamWaitEvent(0, e_w, 0);
    k_gemm_qk<<<dim3(16, 128), 256, QK_NS * QK_STAGE, 0>>>();
    k_attn<<<64, 256, 0, 0>>>(c1, c2);
    k_ode <<<8, 256, 0, 0>>>(conv1_w, gn_g, gn_b, conv2_w, conv2_b);

    // join M_b, final gemm (fused softmax-scale epilogue — no extra traffic)
    cudaStreamWaitEvent(0, e_mb, 0);
    k_gemm2<<<dim3(8, 128), 256, G2_NS * G2_STAGE, 0>>>(proj_b, out);
}